// round 15
// baseline (speedup 1.0000x reference)
#include <cuda_runtime.h>
#include <cuda_fp16.h>
#include <cstdint>
#include <math.h>

#define HID 256
#define SPB 4           // samples per block (2 per half)
#define TPB 128         // 4 warps = 2 independent halves of 2 warps

#define RSA 528         // A smem row stride bytes (264 fp16: 256 + 8 pad)

// ---- dynamic smem offsets (bytes) ----
#define SM_RED   0                          // 64 floats
#define SM_JT    1024                       // 4 warps * 4KB: [zin 1K | h 1K | t 1K | c 1K]
#define SM_AH    (SM_JT + 16384)            // 17408 ; rows: half*16 + sil*8 + ch
#define SM_AL    (SM_AH + 32 * RSA)         // 34304
#define SMEM_TOTAL (SM_AL + 32 * RSA)       // 51200 -> 4 blocks/SM

// W (fp16) pre-packed in exact m16n8k16 B-fragment layout:
// uint4 g_wfrag[(l*4 + quarter)*2048 + (ki*4+p)*32 + lane]
__device__ __align__(16) uint4 g_wfrag[3 * 4 * 2048];

// ---------------- helpers ----------------
__device__ __forceinline__ uint32_t smem_u32(const void* p) {
    uint32_t a;
    asm("{ .reg .u64 t; cvta.to.shared.u64 t, %1; cvt.u32.u64 %0, t; }" : "=r"(a) : "l"(p));
    return a;
}
__device__ __forceinline__ void ldsm_x4(uint32_t addr, uint32_t r[4]) {
    asm volatile("ldmatrix.sync.aligned.m8n8.x4.shared.b16 {%0,%1,%2,%3}, [%4];"
                 : "=r"(r[0]), "=r"(r[1]), "=r"(r[2]), "=r"(r[3]) : "r"(addr));
}
__device__ __forceinline__ void mma16816(float d[4], const uint32_t a[4],
                                         uint32_t b0, uint32_t b1) {
    asm volatile("mma.sync.aligned.m16n8k16.row.col.f32.f16.f16.f32 "
                 "{%0,%1,%2,%3},{%4,%5,%6,%7},{%8,%9},{%0,%1,%2,%3};"
                 : "+f"(d[0]), "+f"(d[1]), "+f"(d[2]), "+f"(d[3])
                 : "r"(a[0]), "r"(a[1]), "r"(a[2]), "r"(a[3]), "r"(b0), "r"(b1));
}
// half-block barrier: 64 threads, ids 1..2
#define HBAR(h) asm volatile("bar.sync %0, 64;" :: "r"(1 + (h)) : "memory")

__device__ __forceinline__ float my_tanhf(float z) {
    float a = fabsf(z);
    float e = __expf(-2.0f * a);
    float t = __fdividef(1.0f - e, 1.0f + e);
    return copysignf(t, z);
}
// fp16 hi/lo exact 2-way split of two floats via packed f16x2 converts
__device__ __forceinline__ void split_pack(float a, float b, uint32_t& hi, uint32_t& lo) {
    __half2 h = __floats2half2_rn(a, b);
    float2 hf = __half22float2(h);
    __half2 l = __floats2half2_rn(a - hf.x, b - hf.y);
    hi = *(uint32_t*)&h;
    lo = *(uint32_t*)&l;
}
__device__ __forceinline__ void storeA(char* smem, int m, int nc, float v0, float v1) {
    uint32_t hi, lo; split_pack(v0, v1, hi, lo);
    int off = m * RSA + nc * 2;
    *(uint32_t*)(smem + SM_AH + off) = hi;
    *(uint32_t*)(smem + SM_AL + off) = lo;
}

// ---------------- prep: W -> fp16 B-fragment layout ----------------
__global__ void prep_w_kernel(const float* __restrict__ W1, const float* __restrict__ W2,
                              const float* __restrict__ W3) {
    int idx = blockIdx.x * blockDim.x + threadIdx.x;
    if (idx >= 3 * 32768) return;
    int l    = idx >> 15;
    int rem  = idx & 32767;
    int nt16 = rem >> 11;
    int ki   = (rem >> 7) & 15;
    int r    = (rem >> 5) & 3;
    int lane = rem & 31;
    int n = nt16 * 16 + ((r >> 1) << 3) + (lane >> 2);
    int k = ki * 16 + ((r & 1) << 3) + ((lane & 3) << 1);
    const float* W = (l == 0) ? W1 : (l == 1) ? W2 : W3;
    float v0 = W[k * HID + n];
    float v1 = W[(k + 1) * HID + n];
    __half h0 = __float2half_rn(v0), h1 = __float2half_rn(v1);
    uint32_t hip = (uint32_t)__half_as_ushort(h0) | ((uint32_t)__half_as_ushort(h1) << 16);
    int ntq = nt16 >> 2, p = nt16 & 3;
    int slot = ((ki * 4 + p) * 32 + lane) * 4 + r;
    uint32_t* w32 = (uint32_t*)g_wfrag;
    w32[((l * 4 + ntq) * 2048) * 4 + slot] = hip;
}

// ---------------- main kernel ----------------
__global__ __launch_bounds__(TPB, 4) void pinn_mma_kernel(
    const float* __restrict__ x,
    const float* __restrict__ W0, const float* __restrict__ b0,
    const float* __restrict__ b1, const float* __restrict__ b2,
    const float* __restrict__ b3,
    const float* __restrict__ Wout, const float* __restrict__ bout,
    float* __restrict__ out, int B)
{
    extern __shared__ char smem[];
    const uint32_t sb = smem_u32(smem);
    const int tid = threadIdx.x, wid = tid >> 5, lane = tid & 31;
    const int base = blockIdx.x * SPB;

    // -------- layer 0: analytic jets -> A (rows m = s*8 + ch), full block ----
    {
        const int nc = tid * 2;
        float wa0 = __ldg(&W0[nc]),     wa1 = __ldg(&W0[HID + nc]),     wa2 = __ldg(&W0[2*HID + nc]);
        float wb0 = __ldg(&W0[nc + 1]), wb1 = __ldg(&W0[HID + nc + 1]), wb2 = __ldg(&W0[2*HID + nc + 1]);
        float ba = __ldg(&b0[nc]), bb = __ldg(&b0[nc + 1]);
        #pragma unroll
        for (int s = 0; s < SPB; s++) {
            int idx = base + s; if (idx >= B) idx = B - 1;
            float x0 = __ldg(&x[idx*3]), x1 = __ldg(&x[idx*3+1]), x2 = __ldg(&x[idx*3+2]);
            float za = fmaf(x2, wa2, fmaf(x1, wa1, fmaf(x0, wa0, ba)));
            float zb = fmaf(x2, wb2, fmaf(x1, wb1, fmaf(x0, wb0, bb)));
            float hA = my_tanhf(za), tA = 1.f - hA*hA, cA = -2.f*hA*tA;
            float hB = my_tanhf(zb), tB = 1.f - hB*hB, cB = -2.f*hB*tB;
            float va[8] = {hA, tA*wa0, tA*wa1, tA*wa2, cA*wa0*wa0, cA*wa1*wa1, cA*wa2*wa2, 0.f};
            float vb[8] = {hB, tB*wb0, tB*wb1, tB*wb2, cB*wb0*wb0, cB*wb1*wb1, cB*wb2*wb2, 0.f};
            #pragma unroll
            for (int c = 0; c < 8; c++) storeA(smem, s * 8 + c, nc, va[c], vb[c]);
        }
    }
    __syncthreads();

    // half-block tiling: half = wid>>1 owns samples base+2h..+1, A rows 16h..16h+15
    // warp wh = wid&1 covers n-cols [wh*128, wh*128+128)
    const int half = wid >> 1;
    const int wh = wid & 1;
    const int ncol0 = wh * 128;
    const int ch = lane >> 2;
    const int srcb = lane & 3;
    const uint32_t aOff = (uint32_t)((half * 16 + (lane & 15)) * RSA + (lane >> 4) * 16);
    char* zin = smem + SM_JT + wid * 4096;   // [2 samples][128 cols] fp32
    char* hpl = zin + 1024;
    char* tpl = zin + 2048;
    char* cpl = zin + 3072;

    #pragma unroll 1
    for (int l = 0; l < 3; l++) {
        float acc[16][4];
        #pragma unroll
        for (int nt = 0; nt < 16; nt++)
            { acc[nt][0]=0.f; acc[nt][1]=0.f; acc[nt][2]=0.f; acc[nt][3]=0.f; }

        const uint4* fQ0 = g_wfrag + (uint32_t)(l * 4 + wh * 2) * 2048 + lane;
        const uint4* fQ1 = fQ0 + 2048;

        #pragma unroll 4
        for (int ki = 0; ki < 16; ki++) {
            uint32_t ah[4], al[4];
            const uint32_t akb = (uint32_t)(ki * 32);
            ldsm_x4(sb + SM_AH + aOff + akb, ah);
            ldsm_x4(sb + SM_AL + aOff + akb, al);
            uint4 bq0[4], bq1[4];
            #pragma unroll
            for (int p = 0; p < 4; p++) {
                bq0[p] = __ldg(fQ0 + (ki * 4 + p) * 32);
                bq1[p] = __ldg(fQ1 + (ki * 4 + p) * 32);
            }
            #pragma unroll
            for (int p = 0; p < 4; p++) {
                mma16816(acc[2*p],       ah, bq0[p].x, bq0[p].y);
                mma16816(acc[2*p+1],     ah, bq0[p].z, bq0[p].w);
                mma16816(acc[8+2*p],     ah, bq1[p].x, bq1[p].y);
                mma16816(acc[8+2*p+1],   ah, bq1[p].z, bq1[p].w);
            }
            #pragma unroll
            for (int p = 0; p < 4; p++) {
                mma16816(acc[2*p],       al, bq0[p].x, bq0[p].y);
                mma16816(acc[2*p+1],     al, bq0[p].z, bq0[p].w);
                mma16816(acc[8+2*p],     al, bq1[p].x, bq1[p].y);
                mma16816(acc[8+2*p+1],   al, bq1[p].z, bq1[p].w);
            }
        }
        HBAR(half);   // both warps of half done reading A before pass C overwrites

        // -------- pass A: ch0 lanes dump h-channel z rows (2 samples) --------
        if (ch == 0) {
            #pragma unroll
            for (int nt = 0; nt < 16; nt++) {
                int cq = nt * 8 + srcb * 2;
                *(float2*)(zin + cq * 4)         = make_float2(acc[nt][0], acc[nt][1]);
                *(float2*)(zin + (128 + cq) * 4) = make_float2(acc[nt][2], acc[nt][3]);
            }
        }
        __syncwarp();

        // -------- pass B: 8 distinct tanh per lane --------
        const float* bp = (l == 0) ? b1 : (l == 1) ? b2 : b3;
        {
            const int c0 = (lane & 15) * 8;
            const int sB = lane >> 4;
            float4 za  = *(float4*)(zin + (sB * 128 + c0) * 4);
            float4 zb4 = *(float4*)(zin + (sB * 128 + c0 + 4) * 4);
            float4 bia = __ldg((const float4*)(bp + ncol0 + c0));
            float4 bib = __ldg((const float4*)(bp + ncol0 + c0 + 4));
            float h0 = my_tanhf(za.x + bia.x), h1 = my_tanhf(za.y + bia.y);
            float h2 = my_tanhf(za.z + bia.z), h3 = my_tanhf(za.w + bia.w);
            float h4 = my_tanhf(zb4.x + bib.x), h5 = my_tanhf(zb4.y + bib.y);
            float h6 = my_tanhf(zb4.z + bib.z), h7 = my_tanhf(zb4.w + bib.w);
            float t0 = 1.f-h0*h0, t1 = 1.f-h1*h1, t2 = 1.f-h2*h2, t3 = 1.f-h3*h3;
            float t4 = 1.f-h4*h4, t5 = 1.f-h5*h5, t6 = 1.f-h6*h6, t7 = 1.f-h7*h7;
            const int o1w = (sB * 128 + c0) * 4, o2w = o1w + 16;
            *(float4*)(hpl + o1w) = make_float4(h0, h1, h2, h3);
            *(float4*)(hpl + o2w) = make_float4(h4, h5, h6, h7);
            *(float4*)(tpl + o1w) = make_float4(t0, t1, t2, t3);
            *(float4*)(tpl + o2w) = make_float4(t4, t5, t6, t7);
            *(float4*)(cpl + o1w) = make_float4(-2.f*h0*t0, -2.f*h1*t1, -2.f*h2*t2, -2.f*h3*t3);
            *(float4*)(cpl + o2w) = make_float4(-2.f*h4*t4, -2.f*h5*t5, -2.f*h6*t6, -2.f*h7*t7);
        }
        __syncwarp();

        // -------- pass C: jet transform (tanh-free) ----------
        float accO[2] = {0.f, 0.f};
        const int gsrc = (lane - 12) & 31;
        const char* sp = (ch == 0) ? hpl : tpl;

        #pragma unroll
        for (int nt = 0; nt < 16; nt++) {
            int cq   = nt * 8 + (srcb << 1);
            int ncol = ncol0 + cq;
            float z0 = acc[nt][0], z1 = acc[nt][1];
            float z2 = acc[nt][2], z3 = acc[nt][3];
            float2 pA = *(float2*)(sp  + cq * 4);
            float2 pB = *(float2*)(sp  + (128 + cq) * 4);
            float2 qA = *(float2*)(cpl + cq * 4);
            float2 qB = *(float2*)(cpl + (128 + cq) * 4);
            float zg0 = __shfl_sync(0xffffffffu, z0, gsrc);
            float zg1 = __shfl_sync(0xffffffffu, z1, gsrc);
            float zg2 = __shfl_sync(0xffffffffu, z2, gsrc);
            float zg3 = __shfl_sync(0xffffffffu, z3, gsrc);
            float o0 = (ch == 0) ? pA.x : (ch < 4) ? pA.x * z0
                     : (ch < 7) ? fmaf(qA.x * zg0, zg0, pA.x * z0) : 0.f;
            float o1 = (ch == 0) ? pA.y : (ch < 4) ? pA.y * z1
                     : (ch < 7) ? fmaf(qA.y * zg1, zg1, pA.y * z1) : 0.f;
            float o2 = (ch == 0) ? pB.x : (ch < 4) ? pB.x * z2
                     : (ch < 7) ? fmaf(qB.x * zg2, zg2, pB.x * z2) : 0.f;
            float o3 = (ch == 0) ? pB.y : (ch < 4) ? pB.y * z3
                     : (ch < 7) ? fmaf(qB.y * zg3, zg3, pB.y * z3) : 0.f;
            if (l < 2) {
                storeA(smem, half * 16 + ch,     ncol, o0, o1);
                storeA(smem, half * 16 + ch + 8, ncol, o2, o3);
            } else {
                float w0 = __ldg(&Wout[ncol]), w1 = __ldg(&Wout[ncol + 1]);
                accO[0] = fmaf(o0, w0, fmaf(o1, w1, accO[0]));
                accO[1] = fmaf(o2, w0, fmaf(o3, w1, accO[1]));
            }
        }

        if (l < 2) {
            HBAR(half);   // A writes visible to both warps of half
        } else {
            accO[0] += __shfl_xor_sync(0xffffffffu, accO[0], 1);
            accO[0] += __shfl_xor_sync(0xffffffffu, accO[0], 2);
            accO[1] += __shfl_xor_sync(0xffffffffu, accO[1], 1);
            accO[1] += __shfl_xor_sync(0xffffffffu, accO[1], 2);
            float* red = (float*)(smem + SM_RED);
            if (srcb == 0) {
                red[wid * 16 + ch]     = accO[0];
                red[wid * 16 + 8 + ch] = accO[1];
            }
            HBAR(half);
            if ((tid & 63) < 16) {
                int j = tid & 15;
                float v = red[(half * 2) * 16 + j] + red[(half * 2 + 1) * 16 + j];
                int s = j >> 3, c = j & 7;
                int g = base + half * 2 + s;
                if (c < 7 && g < B) {
                    if (c == 0) v += __ldg(&bout[0]);
                    out[g * 7 + c] = v;
                }
            }
        }
    }
}

extern "C" void kernel_launch(void* const* d_in, const int* in_sizes, int n_in,
                              void* d_out, int out_size)
{
    const float* x    = (const float*)d_in[0];
    const float* W0   = (const float*)d_in[1];
    const float* b0   = (const float*)d_in[2];
    const float* W1   = (const float*)d_in[3];
    const float* b1   = (const float*)d_in[4];
    const float* W2   = (const float*)d_in[5];
    const float* b2   = (const float*)d_in[6];
    const float* W3   = (const float*)d_in[7];
    const float* b3   = (const float*)d_in[8];
    const float* Wout = (const float*)d_in[9];
    const float* bout = (const float*)d_in[10];
    float* out = (float*)d_out;

    const int B = in_sizes[0] / 3;
    const int nblk = (B + SPB - 1) / SPB;

    prep_w_kernel<<<(3 * 32768 + 255) / 256, 256>>>(W1, W2, W3);

    cudaFuncSetAttribute(pinn_mma_kernel,
                         cudaFuncAttributeMaxDynamicSharedMemorySize, SMEM_TOTAL);
    pinn_mma_kernel<<<nblk, TPB, SMEM_TOTAL>>>(x, W0, b0, b1, b2, b3,
                                               Wout, bout, out, B);
}

// round 16
// speedup vs baseline: 1.2788x; 1.2788x over previous
#include <cuda_runtime.h>
#include <cuda_fp16.h>
#include <cstdint>
#include <math.h>

#define HID 256
#define SPB 4           // samples per block -> M = 32 jet rows (row = c*4 + s)
#define TPB 128         // 4 warps, each m32 x n64 (ntq = wid)

#define RSA 528         // A smem row stride bytes (264 fp16: 256 + 8 pad)

// ---- dynamic smem offsets (bytes) ----
#define SM_RED   0                          // 128 floats
#define SM_AH    1024
#define SM_AL    (SM_AH + 32 * RSA)         // 17920
#define SMEM_TOTAL (SM_AL + 32 * RSA)       // 34816 (occupancy reg-capped at 4)

// W (fp16) pre-packed in exact m16n8k16 B-fragment layout:
// uint4 g_wfrag[(l*4 + ntq)*2048 + (ki*4+p)*32 + lane]
__device__ __align__(16) uint4 g_wfrag[3 * 4 * 2048];

// ---------------- helpers ----------------
__device__ __forceinline__ uint32_t smem_u32(const void* p) {
    uint32_t a;
    asm("{ .reg .u64 t; cvta.to.shared.u64 t, %1; cvt.u32.u64 %0, t; }" : "=r"(a) : "l"(p));
    return a;
}
__device__ __forceinline__ void ldsm_x4(uint32_t addr, uint32_t r[4]) {
    asm volatile("ldmatrix.sync.aligned.m8n8.x4.shared.b16 {%0,%1,%2,%3}, [%4];"
                 : "=r"(r[0]), "=r"(r[1]), "=r"(r[2]), "=r"(r[3]) : "r"(addr));
}
__device__ __forceinline__ void mma16816(float d[4], const uint32_t a[4],
                                         uint32_t b0, uint32_t b1) {
    asm volatile("mma.sync.aligned.m16n8k16.row.col.f32.f16.f16.f32 "
                 "{%0,%1,%2,%3},{%4,%5,%6,%7},{%8,%9},{%0,%1,%2,%3};"
                 : "+f"(d[0]), "+f"(d[1]), "+f"(d[2]), "+f"(d[3])
                 : "r"(a[0]), "r"(a[1]), "r"(a[2]), "r"(a[3]), "r"(b0), "r"(b1));
}
__device__ __forceinline__ float my_tanhf(float z) {
    float a = fabsf(z);
    float e = __expf(-2.0f * a);
    float t = __fdividef(1.0f - e, 1.0f + e);
    return copysignf(t, z);
}
// fp16 hi/lo exact 2-way split of two floats via packed f16x2 converts
__device__ __forceinline__ void split_pack(float a, float b, uint32_t& hi, uint32_t& lo) {
    __half2 h = __floats2half2_rn(a, b);
    float2 hf = __half22float2(h);
    __half2 l = __floats2half2_rn(a - hf.x, b - hf.y);
    hi = *(uint32_t*)&h;
    lo = *(uint32_t*)&l;
}
__device__ __forceinline__ void storeA(char* smem, int m, int nc, float v0, float v1) {
    uint32_t hi, lo; split_pack(v0, v1, hi, lo);
    int off = m * RSA + nc * 2;
    *(uint32_t*)(smem + SM_AH + off) = hi;
    *(uint32_t*)(smem + SM_AL + off) = lo;
}

// ---------------- prep: W -> fp16 B-fragment layout ----------------
__global__ void prep_w_kernel(const float* __restrict__ W1, const float* __restrict__ W2,
                              const float* __restrict__ W3) {
    int idx = blockIdx.x * blockDim.x + threadIdx.x;
    if (idx >= 3 * 32768) return;
    int l    = idx >> 15;
    int rem  = idx & 32767;
    int nt16 = rem >> 11;
    int ki   = (rem >> 7) & 15;
    int r    = (rem >> 5) & 3;
    int lane = rem & 31;
    int n = nt16 * 16 + ((r >> 1) << 3) + (lane >> 2);
    int k = ki * 16 + ((r & 1) << 3) + ((lane & 3) << 1);
    const float* W = (l == 0) ? W1 : (l == 1) ? W2 : W3;
    float v0 = W[k * HID + n];
    float v1 = W[(k + 1) * HID + n];
    __half h0 = __float2half_rn(v0), h1 = __float2half_rn(v1);
    uint32_t hip = (uint32_t)__half_as_ushort(h0) | ((uint32_t)__half_as_ushort(h1) << 16);
    int ntq = nt16 >> 2, p = nt16 & 3;
    int slot = ((ki * 4 + p) * 32 + lane) * 4 + r;
    uint32_t* w32 = (uint32_t*)g_wfrag;
    w32[((l * 4 + ntq) * 2048) * 4 + slot] = hip;
}

// ---------------- main kernel ----------------
__global__ __launch_bounds__(TPB, 4) void pinn_mma_kernel(
    const float* __restrict__ x,
    const float* __restrict__ W0, const float* __restrict__ b0,
    const float* __restrict__ b1, const float* __restrict__ b2,
    const float* __restrict__ b3,
    const float* __restrict__ Wout, const float* __restrict__ bout,
    float* __restrict__ out, int B)
{
    extern __shared__ char smem[];
    const uint32_t sb = smem_u32(smem);
    const int tid = threadIdx.x, wid = tid >> 5, lane = tid & 31;
    const int base = blockIdx.x * SPB;

    // -------- layer 0: analytic jets -> A (row = c*4 + s) --------
    {
        const int nc = tid * 2;   // 128 threads cover 256 columns
        float wa0 = __ldg(&W0[nc]),     wa1 = __ldg(&W0[HID + nc]),     wa2 = __ldg(&W0[2*HID + nc]);
        float wb0 = __ldg(&W0[nc + 1]), wb1 = __ldg(&W0[HID + nc + 1]), wb2 = __ldg(&W0[2*HID + nc + 1]);
        float ba = __ldg(&b0[nc]), bb = __ldg(&b0[nc + 1]);
        #pragma unroll
        for (int s = 0; s < SPB; s++) {
            int idx = base + s; if (idx >= B) idx = B - 1;
            float x0 = __ldg(&x[idx*3]), x1 = __ldg(&x[idx*3+1]), x2 = __ldg(&x[idx*3+2]);
            float za = fmaf(x2, wa2, fmaf(x1, wa1, fmaf(x0, wa0, ba)));
            float zb = fmaf(x2, wb2, fmaf(x1, wb1, fmaf(x0, wb0, bb)));
            float hA = my_tanhf(za), tA = 1.f - hA*hA, cA = -2.f*hA*tA;
            float hB = my_tanhf(zb), tB = 1.f - hB*hB, cB = -2.f*hB*tB;
            float va[8] = {hA, tA*wa0, tA*wa1, tA*wa2, cA*wa0*wa0, cA*wa1*wa1, cA*wa2*wa2, 0.f};
            float vb[8] = {hB, tB*wb0, tB*wb1, tB*wb2, cB*wb0*wb0, cB*wb1*wb1, cB*wb2*wb2, 0.f};
            #pragma unroll
            for (int c = 0; c < 8; c++) storeA(smem, c * 4 + s, nc, va[c], vb[c]);
        }
    }
    __syncthreads();

    // warp tiling: each warp = m32 x n64, ntq = wid (4 warps cover n256)
    const int ntq = wid;
    const int ncol0 = ntq * 64;
    const int e = lane >> 4;                  // 0: chans {0,2,4,6}; 1: {1,3,5,7}
    const int s_loc = (lane >> 2) & 3;        // sample within tile
    const int q2 = (lane & 3) * 2;            // col pair offset
    const int r0 = e * 4 + s_loc;             // base A row for stores
    const uint32_t aOff = (uint32_t)((lane & 15) * RSA + (lane >> 4) * 16);

    #pragma unroll 1
    for (int l = 0; l < 3; l++) {
        float acc[2][8][4];
        #pragma unroll
        for (int t = 0; t < 2; t++)
            #pragma unroll
            for (int nt = 0; nt < 8; nt++)
                { acc[t][nt][0]=0.f; acc[t][nt][1]=0.f; acc[t][nt][2]=0.f; acc[t][nt][3]=0.f; }

        const uint4* fH = g_wfrag + (uint32_t)(l * 4 + ntq) * 2048 + lane;

        #pragma unroll 8
        for (int ki = 0; ki < 16; ki++) {
            uint32_t ah[2][4], al[2][4];
            const uint32_t akb = (uint32_t)(ki * 32);
            #pragma unroll
            for (int t = 0; t < 2; t++) {
                ldsm_x4(sb + SM_AH + aOff + (uint32_t)(t * 16 * RSA) + akb, ah[t]);
                ldsm_x4(sb + SM_AL + aOff + (uint32_t)(t * 16 * RSA) + akb, al[t]);
            }
            uint4 bh[4];
            #pragma unroll
            for (int p = 0; p < 4; p++)
                bh[p] = __ldg(fH + (ki * 4 + p) * 32);
            #pragma unroll
            for (int p = 0; p < 4; p++)
                #pragma unroll
                for (int t = 0; t < 2; t++) {
                    mma16816(acc[t][2*p],   ah[t], bh[p].x, bh[p].y);
                    mma16816(acc[t][2*p+1], ah[t], bh[p].z, bh[p].w);
                }
            #pragma unroll
            for (int p = 0; p < 4; p++)
                #pragma unroll
                for (int t = 0; t < 2; t++) {
                    mma16816(acc[t][2*p],   al[t], bh[p].x, bh[p].y);
                    mma16816(acc[t][2*p+1], al[t], bh[p].z, bh[p].w);
                }
        }
        __syncthreads();   // all MMA reads of A done before epilogue overwrites A

        // -------- epilogue: fully in-register jet transform --------
        // tile0 rows = chans 0-3, tile1 rows = chans 4-7 (row = c*4 + s)
        // lane e=0: regs hold {h, g1 | s0, s2}; e=1: {g0, g2 | s1, pad}
        const float* bp = (l == 0) ? b1 : (l == 1) ? b2 : b3;
        float sO[4] = {0.f, 0.f, 0.f, 0.f};

        #pragma unroll
        for (int nt = 0; nt < 8; nt++) {
            int col0 = ncol0 + nt * 8 + q2;
            float z00 = acc[0][nt][0], z01 = acc[0][nt][1];
            float z02 = acc[0][nt][2], z03 = acc[0][nt][3];
            float z10 = acc[1][nt][0], z11 = acc[1][nt][1];
            float z12 = acc[1][nt][2], z13 = acc[1][nt][3];
            // exchange tile0 regs across the e-halves (same sample/cols)
            float w0 = __shfl_xor_sync(0xffffffffu, z00, 16);
            float w1 = __shfl_xor_sync(0xffffffffu, z01, 16);
            float w2 = __shfl_xor_sync(0xffffffffu, z02, 16);
            float w3 = __shfl_xor_sync(0xffffffffu, z03, 16);
            // e=0 computes tanh for col0 (own z_h); e=1 for col1 (partner's z_h)
            float zh = (e == 0) ? z00 : w1;
            float bi = __ldg(&bp[col0 + e]);
            float h  = my_tanhf(zh + bi);
            float tt = 1.f - h * h;
            float cc = -2.f * h * tt;
            float h_o = __shfl_xor_sync(0xffffffffu, h,  16);
            float t_o = __shfl_xor_sync(0xffffffffu, tt, 16);
            float c_o = __shfl_xor_sync(0xffffffffu, cc, 16);
            float t0 = (e == 0) ? tt  : t_o, t1 = (e == 0) ? t_o : tt;
            float c0 = (e == 0) ? cc  : c_o, c1 = (e == 0) ? c_o : cc;
            // outputs: reg01 tile0 -> ch e (h or g0); reg23 tile0 -> ch e+2 (g1/g2)
            float oA0c0 = (e == 0) ? h   : t0 * z00;
            float oA0c1 = (e == 0) ? h_o : t1 * z01;
            float oA1c0 = t0 * z02, oA1c1 = t1 * z03;
            // reg01 tile1 -> ch e+4 (s0/s1): zg = g-of-same-axis from partner regs
            float zgc0 = (e == 0) ? w0 : w2;
            float zgc1 = (e == 0) ? w1 : w3;
            float oB0c0 = fmaf(c0 * zgc0, zgc0, t0 * z10);
            float oB0c1 = fmaf(c1 * zgc1, zgc1, t1 * z11);
            // reg23 tile1 -> ch e+6: e=0 -> s2 (zg2 = partner regs 2,3); e=1 -> pad
            float oB1c0 = fmaf(c0 * w2, w2, t0 * z12);
            float oB1c1 = fmaf(c1 * w3, w3, t1 * z13);

            if (l < 2) {
                storeA(smem, r0,      col0, oA0c0, oA0c1);
                storeA(smem, r0 + 8,  col0, oA1c0, oA1c1);
                storeA(smem, r0 + 16, col0, oB0c0, oB0c1);
                if (e == 0) storeA(smem, r0 + 24, col0, oB1c0, oB1c1);
            } else {
                float wo0 = __ldg(&Wout[col0]), wo1 = __ldg(&Wout[col0 + 1]);
                sO[0] = fmaf(oA0c0, wo0, fmaf(oA0c1, wo1, sO[0]));
                sO[1] = fmaf(oA1c0, wo0, fmaf(oA1c1, wo1, sO[1]));
                sO[2] = fmaf(oB0c0, wo0, fmaf(oB0c1, wo1, sO[2]));
                sO[3] = fmaf(oB1c0, wo0, fmaf(oB1c1, wo1, sO[3]));
            }
        }

        if (l < 2) {
            __syncthreads();   // A stores visible before next layer's LDSM
        } else {
            #pragma unroll
            for (int k = 0; k < 4; k++) {
                sO[k] += __shfl_xor_sync(0xffffffffu, sO[k], 1);
                sO[k] += __shfl_xor_sync(0xffffffffu, sO[k], 2);
            }
            float* red = (float*)(smem + SM_RED);
            if ((lane & 3) == 0) {
                int slot = wid * 32 + s_loc * 8 + e;
                red[slot]     = sO[0];
                red[slot + 2] = sO[1];
                red[slot + 4] = sO[2];
                if (e == 0) red[wid * 32 + s_loc * 8 + 6] = sO[3];
            }
            __syncthreads();
            if (tid < 32) {
                int s = tid >> 3, c = tid & 7;
                if (c < 7) {
                    float v = red[tid] + red[32 + tid] + red[64 + tid] + red[96 + tid];
                    int g = base + s;
                    if (g < B) {
                        if (c == 0) v += __ldg(&bout[0]);
                        out[g * 7 + c] = v;
                    }
                }
            }
        }
    }
}

extern "C" void kernel_launch(void* const* d_in, const int* in_sizes, int n_in,
                              void* d_out, int out_size)
{
    const float* x    = (const float*)d_in[0];
    const float* W0   = (const float*)d_in[1];
    const float* b0   = (const float*)d_in[2];
    const float* W1   = (const float*)d_in[3];
    const float* b1   = (const float*)d_in[4];
    const float* W2   = (const float*)d_in[5];
    const float* b2   = (const float*)d_in[6];
    const float* W3   = (const float*)d_in[7];
    const float* b3   = (const float*)d_in[8];
    const float* Wout = (const float*)d_in[9];
    const float* bout = (const float*)d_in[10];
    float* out = (float*)d_out;

    const int B = in_sizes[0] / 3;
    const int nblk = (B + SPB - 1) / SPB;

    prep_w_kernel<<<(3 * 32768 + 255) / 256, 256>>>(W1, W2, W3);

    cudaFuncSetAttribute(pinn_mma_kernel,
                         cudaFuncAttributeMaxDynamicSharedMemorySize, SMEM_TOTAL);
    pinn_mma_kernel<<<nblk, TPB, SMEM_TOTAL>>>(x, W0, b0, b1, b2, b3,
                                               Wout, bout, out, B);
}

// round 17
// speedup vs baseline: 2.0376x; 1.5934x over previous
#include <cuda_runtime.h>
#include <cuda_fp16.h>
#include <cstdint>
#include <math.h>

#define HID 256
#define SPB 4           // samples per block -> M = 32 jet rows (row = c*4 + s)
#define TPB 128         // 4 warps, each m32 x n64 (ntq = wid)

#define RSA 528         // A smem row stride bytes (264 fp16: 256 + 8 pad)

// ---- dynamic smem offsets (bytes) ----
#define SM_RED   0                          // 128 floats
#define SM_AH    1024
#define SMEM_TOTAL (SM_AH + 32 * RSA)       // 17920 B

// W (fp16) pre-packed in exact m16n8k16 B-fragment layout:
// uint4 g_wfrag[(l*4 + ntq)*2048 + (ki*4+p)*32 + lane]
__device__ __align__(16) uint4 g_wfrag[3 * 4 * 2048];

// ---------------- helpers ----------------
__device__ __forceinline__ uint32_t smem_u32(const void* p) {
    uint32_t a;
    asm("{ .reg .u64 t; cvta.to.shared.u64 t, %1; cvt.u32.u64 %0, t; }" : "=r"(a) : "l"(p));
    return a;
}
__device__ __forceinline__ void ldsm_x4(uint32_t addr, uint32_t r[4]) {
    asm volatile("ldmatrix.sync.aligned.m8n8.x4.shared.b16 {%0,%1,%2,%3}, [%4];"
                 : "=r"(r[0]), "=r"(r[1]), "=r"(r[2]), "=r"(r[3]) : "r"(addr));
}
__device__ __forceinline__ void mma16816(float d[4], const uint32_t a[4],
                                         uint32_t b0, uint32_t b1) {
    asm volatile("mma.sync.aligned.m16n8k16.row.col.f32.f16.f16.f32 "
                 "{%0,%1,%2,%3},{%4,%5,%6,%7},{%8,%9},{%0,%1,%2,%3};"
                 : "+f"(d[0]), "+f"(d[1]), "+f"(d[2]), "+f"(d[3])
                 : "r"(a[0]), "r"(a[1]), "r"(a[2]), "r"(a[3]), "r"(b0), "r"(b1));
}
__device__ __forceinline__ float my_tanhf(float z) {
    float a = fabsf(z);
    float e = __expf(-2.0f * a);
    float t = __fdividef(1.0f - e, 1.0f + e);
    return copysignf(t, z);
}
// single-plane fp16 pack of two floats
__device__ __forceinline__ void storeA(char* smem, int m, int nc, float v0, float v1) {
    __half2 h = __floats2half2_rn(v0, v1);
    *(uint32_t*)(smem + SM_AH + m * RSA + nc * 2) = *(uint32_t*)&h;
}

// ---------------- prep: W -> fp16 B-fragment layout ----------------
__global__ void prep_w_kernel(const float* __restrict__ W1, const float* __restrict__ W2,
                              const float* __restrict__ W3) {
    int idx = blockIdx.x * blockDim.x + threadIdx.x;
    if (idx >= 3 * 32768) return;
    int l    = idx >> 15;
    int rem  = idx & 32767;
    int nt16 = rem >> 11;
    int ki   = (rem >> 7) & 15;
    int r    = (rem >> 5) & 3;
    int lane = rem & 31;
    int n = nt16 * 16 + ((r >> 1) << 3) + (lane >> 2);
    int k = ki * 16 + ((r & 1) << 3) + ((lane & 3) << 1);
    const float* W = (l == 0) ? W1 : (l == 1) ? W2 : W3;
    float v0 = W[k * HID + n];
    float v1 = W[(k + 1) * HID + n];
    __half h0 = __float2half_rn(v0), h1 = __float2half_rn(v1);
    uint32_t hip = (uint32_t)__half_as_ushort(h0) | ((uint32_t)__half_as_ushort(h1) << 16);
    int ntq = nt16 >> 2, p = nt16 & 3;
    int slot = ((ki * 4 + p) * 32 + lane) * 4 + r;
    uint32_t* w32 = (uint32_t*)g_wfrag;
    w32[((l * 4 + ntq) * 2048) * 4 + slot] = hip;
}

// ---------------- main kernel ----------------
__global__ __launch_bounds__(TPB, 4) void pinn_mma_kernel(
    const float* __restrict__ x,
    const float* __restrict__ W0, const float* __restrict__ b0,
    const float* __restrict__ b1, const float* __restrict__ b2,
    const float* __restrict__ b3,
    const float* __restrict__ Wout, const float* __restrict__ bout,
    float* __restrict__ out, int B)
{
    extern __shared__ char smem[];
    const uint32_t sb = smem_u32(smem);
    const int tid = threadIdx.x, wid = tid >> 5, lane = tid & 31;
    const int base = blockIdx.x * SPB;

    // -------- layer 0: analytic jets -> A (row = c*4 + s) --------
    {
        const int nc = tid * 2;   // 128 threads cover 256 columns
        float wa0 = __ldg(&W0[nc]),     wa1 = __ldg(&W0[HID + nc]),     wa2 = __ldg(&W0[2*HID + nc]);
        float wb0 = __ldg(&W0[nc + 1]), wb1 = __ldg(&W0[HID + nc + 1]), wb2 = __ldg(&W0[2*HID + nc + 1]);
        float ba = __ldg(&b0[nc]), bb = __ldg(&b0[nc + 1]);
        #pragma unroll
        for (int s = 0; s < SPB; s++) {
            int idx = base + s; if (idx >= B) idx = B - 1;
            float x0 = __ldg(&x[idx*3]), x1 = __ldg(&x[idx*3+1]), x2 = __ldg(&x[idx*3+2]);
            float za = fmaf(x2, wa2, fmaf(x1, wa1, fmaf(x0, wa0, ba)));
            float zb = fmaf(x2, wb2, fmaf(x1, wb1, fmaf(x0, wb0, bb)));
            float hA = my_tanhf(za), tA = 1.f - hA*hA, cA = -2.f*hA*tA;
            float hB = my_tanhf(zb), tB = 1.f - hB*hB, cB = -2.f*hB*tB;
            float va[8] = {hA, tA*wa0, tA*wa1, tA*wa2, cA*wa0*wa0, cA*wa1*wa1, cA*wa2*wa2, 0.f};
            float vb[8] = {hB, tB*wb0, tB*wb1, tB*wb2, cB*wb0*wb0, cB*wb1*wb1, cB*wb2*wb2, 0.f};
            #pragma unroll
            for (int c = 0; c < 8; c++) storeA(smem, c * 4 + s, nc, va[c], vb[c]);
        }
    }
    __syncthreads();

    // warp tiling: each warp = m32 x n64, ntq = wid (4 warps cover n256)
    const int ntq = wid;
    const int ncol0 = ntq * 64;
    const int e = lane >> 4;                  // 0: chans {0,2,4,6}; 1: {1,3,5,7}
    const int s_loc = (lane >> 2) & 3;        // sample within tile
    const int q2 = (lane & 3) * 2;            // col pair offset
    const int r0 = e * 4 + s_loc;             // base A row for stores
    const uint32_t aOff = (uint32_t)((lane & 15) * RSA + (lane >> 4) * 16);

    #pragma unroll 1
    for (int l = 0; l < 3; l++) {
        float acc[2][8][4];
        #pragma unroll
        for (int t = 0; t < 2; t++)
            #pragma unroll
            for (int nt = 0; nt < 8; nt++)
                { acc[t][nt][0]=0.f; acc[t][nt][1]=0.f; acc[t][nt][2]=0.f; acc[t][nt][3]=0.f; }

        const uint4* fH = g_wfrag + (uint32_t)(l * 4 + ntq) * 2048 + lane;

        #pragma unroll 8
        for (int ki = 0; ki < 16; ki++) {
            uint32_t ah[2][4];
            const uint32_t akb = (uint32_t)(ki * 32);
            #pragma unroll
            for (int t = 0; t < 2; t++)
                ldsm_x4(sb + SM_AH + aOff + (uint32_t)(t * 16 * RSA) + akb, ah[t]);
            uint4 bh[4];
            #pragma unroll
            for (int p = 0; p < 4; p++)
                bh[p] = __ldg(fH + (ki * 4 + p) * 32);
            #pragma unroll
            for (int p = 0; p < 4; p++)
                #pragma unroll
                for (int t = 0; t < 2; t++) {
                    mma16816(acc[t][2*p],   ah[t], bh[p].x, bh[p].y);
                    mma16816(acc[t][2*p+1], ah[t], bh[p].z, bh[p].w);
                }
        }
        __syncthreads();   // all MMA reads of A done before epilogue overwrites A

        // -------- epilogue: fully in-register jet transform --------
        // tile0 rows = chans 0-3, tile1 rows = chans 4-7 (row = c*4 + s)
        // lane e=0: regs hold {h, g1 | s0, s2}; e=1: {g0, g2 | s1, pad}
        const float* bp = (l == 0) ? b1 : (l == 1) ? b2 : b3;
        float sO[4] = {0.f, 0.f, 0.f, 0.f};

        #pragma unroll
        for (int nt = 0; nt < 8; nt++) {
            int col0 = ncol0 + nt * 8 + q2;
            float z00 = acc[0][nt][0], z01 = acc[0][nt][1];
            float z02 = acc[0][nt][2], z03 = acc[0][nt][3];
            float z10 = acc[1][nt][0], z11 = acc[1][nt][1];
            float z12 = acc[1][nt][2], z13 = acc[1][nt][3];
            // exchange tile0 regs across the e-halves (same sample/cols)
            float w0 = __shfl_xor_sync(0xffffffffu, z00, 16);
            float w1 = __shfl_xor_sync(0xffffffffu, z01, 16);
            float w2 = __shfl_xor_sync(0xffffffffu, z02, 16);
            float w3 = __shfl_xor_sync(0xffffffffu, z03, 16);
            // e=0 computes tanh for col0 (own z_h); e=1 for col1 (partner's z_h)
            float zh = (e == 0) ? z00 : w1;
            float bi = __ldg(&bp[col0 + e]);
            float h  = my_tanhf(zh + bi);
            float tt = 1.f - h * h;
            float cc = -2.f * h * tt;
            float h_o = __shfl_xor_sync(0xffffffffu, h,  16);
            float t_o = __shfl_xor_sync(0xffffffffu, tt, 16);
            float c_o = __shfl_xor_sync(0xffffffffu, cc, 16);
            float t0 = (e == 0) ? tt  : t_o, t1 = (e == 0) ? t_o : tt;
            float c0 = (e == 0) ? cc  : c_o, c1 = (e == 0) ? c_o : cc;
            // outputs: reg01 tile0 -> ch e (h or g0); reg23 tile0 -> ch e+2 (g1/g2)
            float oA0c0 = (e == 0) ? h   : t0 * z00;
            float oA0c1 = (e == 0) ? h_o : t1 * z01;
            float oA1c0 = t0 * z02, oA1c1 = t1 * z03;
            // reg01 tile1 -> ch e+4 (s0/s1): zg = g-of-same-axis from partner regs
            float zgc0 = (e == 0) ? w0 : w2;
            float zgc1 = (e == 0) ? w1 : w3;
            float oB0c0 = fmaf(c0 * zgc0, zgc0, t0 * z10);
            float oB0c1 = fmaf(c1 * zgc1, zgc1, t1 * z11);
            // reg23 tile1 -> ch e+6: e=0 -> s2 (zg2 = partner regs 2,3); e=1 -> pad
            float oB1c0 = fmaf(c0 * w2, w2, t0 * z12);
            float oB1c1 = fmaf(c1 * w3, w3, t1 * z13);

            if (l < 2) {
                storeA(smem, r0,      col0, oA0c0, oA0c1);
                storeA(smem, r0 + 8,  col0, oA1c0, oA1c1);
                storeA(smem, r0 + 16, col0, oB0c0, oB0c1);
                if (e == 0) storeA(smem, r0 + 24, col0, oB1c0, oB1c1);
            } else {
                float wo0 = __ldg(&Wout[col0]), wo1 = __ldg(&Wout[col0 + 1]);
                sO[0] = fmaf(oA0c0, wo0, fmaf(oA0c1, wo1, sO[0]));
                sO[1] = fmaf(oA1c0, wo0, fmaf(oA1c1, wo1, sO[1]));
                sO[2] = fmaf(oB0c0, wo0, fmaf(oB0c1, wo1, sO[2]));
                sO[3] = fmaf(oB1c0, wo0, fmaf(oB1c1, wo1, sO[3]));
            }
        }

        if (l < 2) {
            __syncthreads();   // A stores visible before next layer's LDSM
        } else {
            #pragma unroll
            for (int k = 0; k < 4; k++) {
                sO[k] += __shfl_xor_sync(0xffffffffu, sO[k], 1);
                sO[k] += __shfl_xor_sync(0xffffffffu, sO[k], 2);
            }
            float* red = (float*)(smem + SM_RED);
            if ((lane & 3) == 0) {
                int slot = wid * 32 + s_loc * 8 + e;
                red[slot]     = sO[0];
                red[slot + 2] = sO[1];
                red[slot + 4] = sO[2];
                if (e == 0) red[wid * 32 + s_loc * 8 + 6] = sO[3];
            }
            __syncthreads();
            if (tid < 32) {
                int s = tid >> 3, c = tid & 7;
                if (c < 7) {
                    float v = red[tid] + red[32 + tid] + red[64 + tid] + red[96 + tid];
                    int g = base + s;
                    if (g < B) {
                        if (c == 0) v += __ldg(&bout[0]);
                        out[g * 7 + c] = v;
                    }
                }
            }
        }
    }
}

extern "C" void kernel_launch(void* const* d_in, const int* in_sizes, int n_in,
                              void* d_out, int out_size)
{
    const float* x    = (const float*)d_in[0];
    const float* W0   = (const float*)d_in[1];
    const float* b0   = (const float*)d_in[2];
    const float* W1   = (const float*)d_in[3];
    const float* b1   = (const float*)d_in[4];
    const float* W2   = (const float*)d_in[5];
    const float* b2   = (const float*)d_in[6];
    const float* W3   = (const float*)d_in[7];
    const float* b3   = (const float*)d_in[8];
    const float* Wout = (const float*)d_in[9];
    const float* bout = (const float*)d_in[10];
    float* out = (float*)d_out;

    const int B = in_sizes[0] / 3;
    const int nblk = (B + SPB - 1) / SPB;

    prep_w_kernel<<<(3 * 32768 + 255) / 256, 256>>>(W1, W2, W3);

    cudaFuncSetAttribute(pinn_mma_kernel,
                         cudaFuncAttributeMaxDynamicSharedMemorySize, SMEM_TOTAL);
    pinn_mma_kernel<<<nblk, TPB, SMEM_TOTAL>>>(x, W0, b0, b1, b2, b3,
                                               Wout, bout, out, B);
}